// round 9
// baseline (speedup 1.0000x reference)
#include <cuda_runtime.h>
#include <cuda_bf16.h>

#define BMAX 32
#define NMAX 640
#define GMAX 512        // max frame-groups per batch
#define TMAXT 4096      // max total_time supported by scratch
#define TB   8          // frames per block
#define NT   128        // threads per block (E = 384 = 3*NT)

// Scratch (allocation-free rule: __device__ globals)
__device__ float g_c[BMAX][NMAX];      // compacted token centers
__device__ float g_rsig[BMAX][NMAX];   // 1/sigma
__device__ float g_coef[BMAX][NMAX];   // 1/(sigma*sqrt(2pi))
__device__ int   g_tok[BMAX][NMAX];    // merged token ids (compacted)
__device__ float g_cumtot[BMAX];       // total duration per batch
__device__ int2  g_win[BMAX][GMAX];    // per frame-group token window [nlo, nhi]
__device__ float g_sinv[BMAX][TMAXT];  // per-frame 1/(sum_w+eps), 0 if invalid

// ---------------------------------------------------------------------------
// Kernel 1 (fused): merge pairs + shuffle-scan cumsum + compaction of
// zero-weight tokens (pad or zero-duration contribute EXACTLY 0 weight:
// sigma=1e-6 gives |z|>=5e5 so expf underflows to 0 in fp32, matching the
// reference's own underflow) + per-group window binary search in shared mem.
// One block per batch, 1024 threads.
// ---------------------------------------------------------------------------
__global__ void __launch_bounds__(1024)
prep_kernel(const int* __restrict__ text,
            const int* __restrict__ durs,
            int L, int N, int G) {
    const int b    = blockIdx.x;
    const int tid  = threadIdx.x;
    const int wrp  = tid >> 5;
    const int lane = tid & 31;

    float dm = 0.f;
    int   tk = 0;
    if (tid < N) {
        if (tid == 0) {
            dm = (float)durs[b * L];
            tk = text[b * L];
        } else {
            dm = (float)(durs[b * L + 2 * tid - 1] + durs[b * L + 2 * tid]);
            tk = text[b * L + 2 * tid - 1];
        }
    }
    const int keep = (tid < N && tk != 0 && dm > 0.f) ? 1 : 0;

    // ---- two-level inclusive scan over (dm, keep) via shuffles ----
    __shared__ float s_wd[32];
    __shared__ int   s_wk[32];
    float cum = dm;
    int   pos = keep;
    #pragma unroll
    for (int off = 1; off < 32; off <<= 1) {
        float fv = __shfl_up_sync(0xffffffffu, cum, off);
        int   iv = __shfl_up_sync(0xffffffffu, pos, off);
        if (lane >= off) { cum += fv; pos += iv; }
    }
    if (lane == 31) { s_wd[wrp] = cum; s_wk[wrp] = pos; }
    __syncthreads();
    if (wrp == 0) {
        float fv = s_wd[lane];
        int   iv = s_wk[lane];
        #pragma unroll
        for (int off = 1; off < 32; off <<= 1) {
            float f2 = __shfl_up_sync(0xffffffffu, fv, off);
            int   i2 = __shfl_up_sync(0xffffffffu, iv, off);
            if (lane >= off) { fv += f2; iv += i2; }
        }
        s_wd[lane] = fv; s_wk[lane] = iv;
    }
    __syncthreads();
    if (wrp > 0) { cum += s_wd[wrp - 1]; pos += s_wk[wrp - 1]; }

    // ---- emit compacted token params ----
    __shared__ float s_c[NMAX];
    __shared__ int   s_n2;
    if (keep) {
        const int   o   = pos - 1;
        const float sig = dm * 0.5f + 1e-6f;     // d / SIGMA_C + EPS, SIGMA_C = 2
        const float c   = cum - 0.5f * dm;
        g_c[b][o]    = c;
        g_rsig[b][o] = 1.0f / sig;
        g_coef[b][o] = 0.3989422804014327f / sig;
        g_tok[b][o]  = tk;
        s_c[o]       = c;
    }
    if (tid == N - 1) { g_cumtot[b] = cum; s_n2 = pos; }
    __syncthreads();

    // ---- per frame-group windows via binary search in shared centers ----
    // Window |t-c| <= 18: truncated tokens contribute <= ~1e-7 relative
    // (every valid frame has a contributor within ~6 frames, w >= 0.018).
    if (tid < G) {
        const int   N2  = s_n2;
        const float t0f = (float)(tid * TB);
        const float tlo = t0f + 0.5f - 18.f;
        const float thi = t0f + ((float)TB - 0.5f) + 18.f;
        int lo = 0, hi = N2;
        while (lo < hi) { int m = (lo + hi) >> 1; if (s_c[m] < tlo) lo = m + 1; else hi = m; }
        const int nlo = lo;
        hi = N2;
        while (lo < hi) { int m = (lo + hi) >> 1; if (s_c[m] <= thi) lo = m + 1; else hi = m; }
        g_win[b][tid] = make_int2(nlo, lo - 1);
    }
}

// ---------------------------------------------------------------------------
// Kernel 1c: per-frame normalization factor. One thread per (b, t); sums the
// SAME windowed raw weights lenreg will use, writes 1/(sum+eps) (0 beyond the
// sample's duration). 65536 independent threads -> latency fully overlapped.
// ---------------------------------------------------------------------------
__global__ void __launch_bounds__(256)
norm_kernel(int T) {
    const int b = blockIdx.y;
    const int t = blockIdx.x * 256 + threadIdx.x;
    if (t >= T) return;

    const float tf = (float)t + 0.5f;
    float sinv = 0.f;
    if (tf < g_cumtot[b]) {
        const int2 win = g_win[b][t / TB];
        const float* __restrict__ cb    = g_c[b];
        const float* __restrict__ rsigb = g_rsig[b];
        const float* __restrict__ coefb = g_coef[b];
        float sum = 0.f;
        for (int n = win.x; n <= win.y; n++) {
            float z = (tf - cb[n]) * rsigb[n];
            sum += coefb[n] * __expf(-0.5f * z * z);
        }
        sinv = 1.0f / (sum + 1e-6f);
    }
    g_sinv[b][t] = sinv;
}

// ---------------------------------------------------------------------------
// Kernel 2: one block per (b, 8 frames). 128 threads; thread owns output dims
// {tid, tid+128, tid+256} for all 8 frames (24 accumulators). Weights are
// PRE-NORMALIZED at staging (sinv folded in), so the j-loop is pure FMA:
// 3 LDG + 2 LDS.128 + 24 FFMA per token. Epilogue is plain stores.
// ---------------------------------------------------------------------------
__global__ void __launch_bounds__(NT)
lenreg_kernel(const float* __restrict__ emb,
              float* __restrict__ out,
              int T) {
    const int b   = blockIdx.y;
    const int t0  = blockIdx.x * TB;
    const int tid = threadIdx.x;

    float* obase = out + ((size_t)b * T + t0) * 384;
    const float cumtot = g_cumtot[b];

    // Entire block beyond sample duration -> zeros and exit (~25% of blocks)
    if ((float)t0 + 0.5f >= cumtot) {
        #pragma unroll
        for (int tt = 0; tt < TB; tt++) {
            float* orow = obase + tt * 384;
            orow[tid] = 0.f; orow[tid + 128] = 0.f; orow[tid + 256] = 0.f;
        }
        return;
    }

    const float* __restrict__ cb    = g_c[b];
    const float* __restrict__ rsigb = g_rsig[b];
    const float* __restrict__ coefb = g_coef[b];
    const int*   __restrict__ tokb  = g_tok[b];

    const int2  win = g_win[b][blockIdx.x];
    const int   nlo = win.x;
    const int   nhi = win.y;
    const float t0f = (float)t0;

    // Per-frame normalization factors (uniform broadcast loads)
    const float4 si0 = *(const float4*)&g_sinv[b][t0];
    const float4 si1 = *(const float4*)&g_sinv[b][t0 + 4];

    __shared__ float4 Wt4[NT * 2];     // [token][frame/4] normalized weights
    __shared__ int    off_s[NT];       // byte offsets into emb table

    float a0[TB], a1[TB], a2[TB];
    #pragma unroll
    for (int tt = 0; tt < TB; tt++) { a0[tt] = 0.f; a1[tt] = 0.f; a2[tt] = 0.f; }

    for (int base = nlo; base <= nhi; base += NT) {
        const int n = base + tid;
        // ---- stage pre-normalized weights for own token (runs once: the
        //      compacted window holds <= 45 tokens) ----
        if (n <= nhi) {
            const float c  = cb[n];
            const float rs = rsigb[n];
            const float cf = coefb[n];
            float w[TB];
            #pragma unroll
            for (int tt = 0; tt < TB; tt++) {
                float z = (t0f + (float)tt + 0.5f - c) * rs;
                w[tt] = cf * __expf(-0.5f * z * z);
            }
            Wt4[tid * 2 + 0] = make_float4(w[0] * si0.x, w[1] * si0.y,
                                           w[2] * si0.z, w[3] * si0.w);
            Wt4[tid * 2 + 1] = make_float4(w[4] * si1.x, w[5] * si1.y,
                                           w[6] * si1.z, w[7] * si1.w);
            off_s[tid] = tokb[n] * 1536;   // *384 floats *4 bytes
        }
        __syncthreads();

        const int cnt = min(NT, nhi - base + 1);

        // ---- accumulate: 24 FFMA per token against 3 embedding loads ----
        #pragma unroll 2
        for (int j = 0; j < cnt; j++) {
            const float* er = (const float*)((const char*)emb + off_s[j]);
            const float e0 = er[tid];
            const float e1 = er[tid + 128];
            const float e2 = er[tid + 256];
            const float4 w0 = Wt4[j * 2 + 0];
            const float4 w1 = Wt4[j * 2 + 1];
            a0[0] += w0.x * e0; a0[1] += w0.y * e0; a0[2] += w0.z * e0; a0[3] += w0.w * e0;
            a0[4] += w1.x * e0; a0[5] += w1.y * e0; a0[6] += w1.z * e0; a0[7] += w1.w * e0;
            a1[0] += w0.x * e1; a1[1] += w0.y * e1; a1[2] += w0.z * e1; a1[3] += w0.w * e1;
            a1[4] += w1.x * e1; a1[5] += w1.y * e1; a1[6] += w1.z * e1; a1[7] += w1.w * e1;
            a2[0] += w0.x * e2; a2[1] += w0.y * e2; a2[2] += w0.z * e2; a2[3] += w0.w * e2;
            a2[4] += w1.x * e2; a2[5] += w1.y * e2; a2[6] += w1.z * e2; a2[7] += w1.w * e2;
        }
        if (base + NT <= nhi) __syncthreads();   // only if another chunk follows
    }

    // ---- plain stores (normalization already folded into weights) ----
    #pragma unroll
    for (int tt = 0; tt < TB; tt++) {
        float* orow = obase + tt * 384;
        orow[tid]       = a0[tt];
        orow[tid + 128] = a1[tt];
        orow[tid + 256] = a2[tt];
    }
}

// ---------------------------------------------------------------------------
extern "C" void kernel_launch(void* const* d_in, const int* in_sizes, int n_in,
                              void* d_out, int out_size) {
    const int*   text = (const int*)d_in[0];
    const int*   durs = (const int*)d_in[1];
    const float* emb  = (const float*)d_in[2];
    float* out = (float*)d_out;

    const int B = 32;
    const int L = in_sizes[0] / B;        // 1025
    const int N = (L + 1) / 2;            // 513
    const int T = out_size / (B * 384);   // 2048
    const int G = T / TB;                 // 256 frame-groups per batch

    prep_kernel<<<B, 1024>>>(text, durs, L, N, G);

    dim3 ngrid((T + 255) / 256, B);
    norm_kernel<<<ngrid, 256>>>(T);

    dim3 grid(G, B);
    lenreg_kernel<<<grid, NT>>>(emb, out, T);
}

// round 10
// speedup vs baseline: 1.1782x; 1.1782x over previous
#include <cuda_runtime.h>
#include <cuda_bf16.h>

#define BMAX 32
#define NMAX 640
#define GMAX 512        // max frame-groups per batch
#define TB   8          // frames per block
#define NT   96         // threads per block (E = 384 = 4*NT)

// Scratch (allocation-free rule: __device__ globals)
__device__ float g_c[BMAX][NMAX];      // compacted token centers
__device__ float g_rsig[BMAX][NMAX];   // 1/sigma
__device__ float g_coef[BMAX][NMAX];   // 1/(sigma*sqrt(2pi))
__device__ int   g_tok[BMAX][NMAX];    // merged token ids (compacted)
__device__ float g_cumtot[BMAX];       // total duration per batch
__device__ int2  g_win[BMAX][GMAX];    // per frame-group token window [nlo, nhi]

// ---------------------------------------------------------------------------
// Kernel 1 (fused): merge pairs + shuffle-scan cumsum + compaction of
// zero-weight tokens (pad or zero-duration contribute EXACTLY 0 weight:
// sigma=1e-6 gives |z|>=5e5 so expf underflows to 0 in fp32, matching the
// reference's own underflow) + per-group window binary search in shared mem.
// One block per batch, 1024 threads.
// ---------------------------------------------------------------------------
__global__ void __launch_bounds__(1024)
prep_kernel(const int* __restrict__ text,
            const int* __restrict__ durs,
            int L, int N, int G) {
    const int b    = blockIdx.x;
    const int tid  = threadIdx.x;
    const int wrp  = tid >> 5;
    const int lane = tid & 31;

    float dm = 0.f;
    int   tk = 0;
    if (tid < N) {
        if (tid == 0) {
            dm = (float)durs[b * L];
            tk = text[b * L];
        } else {
            dm = (float)(durs[b * L + 2 * tid - 1] + durs[b * L + 2 * tid]);
            tk = text[b * L + 2 * tid - 1];
        }
    }
    const int keep = (tid < N && tk != 0 && dm > 0.f) ? 1 : 0;

    // ---- two-level inclusive scan over (dm, keep) via shuffles ----
    __shared__ float s_wd[32];
    __shared__ int   s_wk[32];
    float cum = dm;
    int   pos = keep;
    #pragma unroll
    for (int off = 1; off < 32; off <<= 1) {
        float fv = __shfl_up_sync(0xffffffffu, cum, off);
        int   iv = __shfl_up_sync(0xffffffffu, pos, off);
        if (lane >= off) { cum += fv; pos += iv; }
    }
    if (lane == 31) { s_wd[wrp] = cum; s_wk[wrp] = pos; }
    __syncthreads();
    if (wrp == 0) {
        float fv = s_wd[lane];
        int   iv = s_wk[lane];
        #pragma unroll
        for (int off = 1; off < 32; off <<= 1) {
            float f2 = __shfl_up_sync(0xffffffffu, fv, off);
            int   i2 = __shfl_up_sync(0xffffffffu, iv, off);
            if (lane >= off) { fv += f2; iv += i2; }
        }
        s_wd[lane] = fv; s_wk[lane] = iv;
    }
    __syncthreads();
    if (wrp > 0) { cum += s_wd[wrp - 1]; pos += s_wk[wrp - 1]; }

    // ---- emit compacted token params ----
    __shared__ float s_c[NMAX];
    __shared__ int   s_n2;
    if (keep) {
        const int   o   = pos - 1;
        const float sig = dm * 0.5f + 1e-6f;     // d / SIGMA_C + EPS, SIGMA_C = 2
        const float c   = cum - 0.5f * dm;
        g_c[b][o]    = c;
        g_rsig[b][o] = 1.0f / sig;
        g_coef[b][o] = 0.3989422804014327f / sig;
        g_tok[b][o]  = tk;
        s_c[o]       = c;
    }
    if (tid == N - 1) { g_cumtot[b] = cum; s_n2 = pos; }
    __syncthreads();

    // ---- per frame-group windows via binary search in shared centers ----
    // Window |t-c| <= 18: truncated tokens contribute <= ~1e-7 relative
    // (every valid frame has a contributor within ~6 frames, w >= 0.018).
    if (tid < G) {
        const int   N2  = s_n2;
        const float t0f = (float)(tid * TB);
        const float tlo = t0f + 0.5f - 18.f;
        const float thi = t0f + ((float)TB - 0.5f) + 18.f;
        int lo = 0, hi = N2;
        while (lo < hi) { int m = (lo + hi) >> 1; if (s_c[m] < tlo) lo = m + 1; else hi = m; }
        const int nlo = lo;
        hi = N2;
        while (lo < hi) { int m = (lo + hi) >> 1; if (s_c[m] <= thi) lo = m + 1; else hi = m; }
        g_win[b][tid] = make_int2(nlo, lo - 1);
    }
}

// ---------------------------------------------------------------------------
// Kernel 2: one block per (b, 8 frames). 96 threads; thread owns ONE float4
// of the embedding dim (E = 384 = 96*4). Hot loop per token: 1 LDG.128 +
// 2 LDS.128 + 32 scalar FFMA. Per-frame weight sums are reduced from shared
// AFTER the loop by threads 0-7 (weights still resident); epilogue scales.
// ---------------------------------------------------------------------------
__global__ void __launch_bounds__(NT)
lenreg_kernel(const float* __restrict__ emb,
              float* __restrict__ out,
              int T) {
    const int b   = blockIdx.y;
    const int t0  = blockIdx.x * TB;
    const int tid = threadIdx.x;

    float4* obase4 = (float4*)(out + ((size_t)b * T + t0) * 384) + tid;
    const float cumtot = g_cumtot[b];

    // Entire block beyond sample duration -> zeros and exit (~25% of blocks)
    if ((float)t0 + 0.5f >= cumtot) {
        const float4 z = make_float4(0.f, 0.f, 0.f, 0.f);
        #pragma unroll
        for (int tt = 0; tt < TB; tt++) obase4[tt * NT] = z;
        return;
    }

    const float* __restrict__ cb    = g_c[b];
    const float* __restrict__ rsigb = g_rsig[b];
    const float* __restrict__ coefb = g_coef[b];
    const int*   __restrict__ tokb  = g_tok[b];

    const int2  win = g_win[b][blockIdx.x];
    const int   nlo = win.x;
    const int   nhi = win.y;
    const float t0f = (float)t0;

    __shared__ float4 Wt4[NT * 2];     // [token][frame/4] raw weights (8 frames)
    __shared__ int    off_s[NT];       // byte offsets into emb table
    __shared__ float  s_inv[TB];

    float4 acc[TB];
    #pragma unroll
    for (int tt = 0; tt < TB; tt++) acc[tt] = make_float4(0.f, 0.f, 0.f, 0.f);
    float ssum = 0.f;                  // running frame sum (threads 0..7 only)

    for (int base = nlo; base <= nhi; base += NT) {
        const int n = base + tid;
        // ---- stage raw weights for own token (compacted window <= 45 tokens,
        //      so this loop body runs once in practice) ----
        if (n <= nhi) {
            const float c  = cb[n];
            const float rs = rsigb[n];
            const float cf = coefb[n];
            float w[TB];
            #pragma unroll
            for (int tt = 0; tt < TB; tt++) {
                float z = (t0f + (float)tt + 0.5f - c) * rs;
                w[tt] = cf * __expf(-0.5f * z * z);
            }
            Wt4[tid * 2 + 0] = make_float4(w[0], w[1], w[2], w[3]);
            Wt4[tid * 2 + 1] = make_float4(w[4], w[5], w[6], w[7]);
            off_s[tid] = tokb[n] * 1536;   // *384 floats *4 bytes
        }
        __syncthreads();

        const int cnt = min(NT, nhi - base + 1);

        // ---- accumulate: 1 LDG.128 + 2 LDS.128 + 32 FFMA per token ----
        #pragma unroll 2
        for (int j = 0; j < cnt; j++) {
            const float4 e = *(const float4*)((const char*)emb + off_s[j] + (tid << 4));
            const float4 w0 = Wt4[j * 2 + 0];
            const float4 w1 = Wt4[j * 2 + 1];
            acc[0].x += w0.x * e.x; acc[0].y += w0.x * e.y; acc[0].z += w0.x * e.z; acc[0].w += w0.x * e.w;
            acc[1].x += w0.y * e.x; acc[1].y += w0.y * e.y; acc[1].z += w0.y * e.z; acc[1].w += w0.y * e.w;
            acc[2].x += w0.z * e.x; acc[2].y += w0.z * e.y; acc[2].z += w0.z * e.z; acc[2].w += w0.z * e.w;
            acc[3].x += w0.w * e.x; acc[3].y += w0.w * e.y; acc[3].z += w0.w * e.z; acc[3].w += w0.w * e.w;
            acc[4].x += w1.x * e.x; acc[4].y += w1.x * e.y; acc[4].z += w1.x * e.z; acc[4].w += w1.x * e.w;
            acc[5].x += w1.y * e.x; acc[5].y += w1.y * e.y; acc[5].z += w1.y * e.z; acc[5].w += w1.y * e.w;
            acc[6].x += w1.z * e.x; acc[6].y += w1.z * e.y; acc[6].z += w1.z * e.z; acc[6].w += w1.z * e.w;
            acc[7].x += w1.w * e.x; acc[7].y += w1.w * e.y; acc[7].z += w1.w * e.z; acc[7].w += w1.w * e.w;
        }

        // ---- per-frame weight sums from the (still resident) staged weights;
        //      thread tt (0..7) owns frame tt, so no cross-thread hazard ----
        if (tid < TB) {
            const float* Wtf = (const float*)Wt4;
            float s = 0.f;
            for (int j = 0; j < cnt; j++) s += Wtf[j * TB + tid];
            ssum += s;
        }
        __syncthreads();   // reduce + loop reads done before Wt reuse / epilogue
    }

    // ---- deferred normalization + 8 STG.128 ----
    if (tid < TB) {
        const bool valid = (t0f + (float)tid + 0.5f) < cumtot;
        s_inv[tid] = valid ? 1.0f / (ssum + 1e-6f) : 0.f;
    }
    __syncthreads();

    #pragma unroll
    for (int tt = 0; tt < TB; tt++) {
        const float inv = s_inv[tt];
        float4 r = acc[tt];
        r.x *= inv; r.y *= inv; r.z *= inv; r.w *= inv;
        obase4[tt * NT] = r;
    }
}

// ---------------------------------------------------------------------------
extern "C" void kernel_launch(void* const* d_in, const int* in_sizes, int n_in,
                              void* d_out, int out_size) {
    const int*   text = (const int*)d_in[0];
    const int*   durs = (const int*)d_in[1];
    const float* emb  = (const float*)d_in[2];
    float* out = (float*)d_out;

    const int B = 32;
    const int L = in_sizes[0] / B;        // 1025
    const int N = (L + 1) / 2;            // 513
    const int T = out_size / (B * 384);   // 2048
    const int G = T / TB;                 // 256 frame-groups per batch

    prep_kernel<<<B, 1024>>>(text, durs, L, N, G);

    dim3 grid(G, B);
    lenreg_kernel<<<grid, NT>>>(emb, out, T);
}